// round 1
// baseline (speedup 1.0000x reference)
#include <cuda_runtime.h>
#include <cuda_bf16.h>

// Pairwise max-margin hinge loss.
// Inputs (metadata order): out [N,B] f32, label [N,B] f32, margin [1] f32.
// Output: scalar f32 = sum_b sum_jk relu(margin - (o_bj-o_bk)*(l_bj-l_bk)) / (N*2)
//
// N=1024, B=32. Layout in gmem is [N,B] row-major, i.e. element (n,b) at n*B+b.

#define PN 1024
#define PB 32

#define JCHUNK 64            // j rows per block
#define NBLK_PER_B (PN / JCHUNK)   // 16
#define THREADS 256
#define KSPLIT (THREADS / JCHUNK)  // 4 k-quarters per j
#define KLEN (PN / KSPLIT)         // 256 k per thread

__global__ __launch_bounds__(THREADS)
void hinge_loss_kernel(const float* __restrict__ g_out,
                       const float* __restrict__ g_label,
                       const float* __restrict__ g_margin,
                       float* __restrict__ result)
{
    __shared__ float2 sm[PN];        // (o_k, l_k) for this batch
    __shared__ float  warp_sums[THREADS / 32];

    const int b      = blockIdx.x / NBLK_PER_B;        // batch index
    const int jbase  = (blockIdx.x % NBLK_PER_B) * JCHUNK;
    const int t      = threadIdx.x;

    // Stage this batch's columns into smem as interleaved float2.
    // g_out[n*B + b]: stride-B gather, hot in L2 after first wave.
    for (int idx = t; idx < PN; idx += THREADS) {
        sm[idx] = make_float2(g_out[idx * PB + b], g_label[idx * PB + b]);
    }
    __syncthreads();

    const float m  = g_margin[0];

    const int j  = jbase + (t & (JCHUNK - 1));
    const int k0 = (t / JCHUNK) * KLEN;

    const float oj = sm[j].x;
    const float lj = sm[j].y;

    float acc = 0.0f;
    // All 32 lanes of a warp share the same k each iteration -> broadcast LDS.64.
    #pragma unroll 8
    for (int k = k0; k < k0 + KLEN; ++k) {
        float2 s = sm[k];
        // margin - (oj-ok)*(lj-lk) == fma(ok-oj, lj-lk, margin)
        float a = s.x - oj;
        float d = lj - s.y;
        float v = fmaf(a, d, m);
        acc += fmaxf(v, 0.0f);
    }

    // Warp reduce
    #pragma unroll
    for (int off = 16; off > 0; off >>= 1)
        acc += __shfl_xor_sync(0xFFFFFFFFu, acc, off);

    const int wid = t >> 5;
    const int lid = t & 31;
    if (lid == 0) warp_sums[wid] = acc;
    __syncthreads();

    if (wid == 0) {
        float s = (lid < THREADS / 32) ? warp_sums[lid] : 0.0f;
        #pragma unroll
        for (int off = 4; off > 0; off >>= 1)
            s += __shfl_xor_sync(0xFFFFFFFFu, s, off);
        if (lid == 0) {
            atomicAdd(result, s * (1.0f / (PN * 2)));
        }
    }
}

extern "C" void kernel_launch(void* const* d_in, const int* in_sizes, int n_in,
                              void* d_out, int out_size)
{
    const float* g_out    = (const float*)d_in[0];
    const float* g_label  = (const float*)d_in[1];
    const float* g_margin = (const float*)d_in[2];
    float*       result   = (float*)d_out;

    // d_out is poisoned to 0xAA; zero it (memset node, graph-capturable).
    cudaMemsetAsync(result, 0, sizeof(float));

    dim3 grid(PB * NBLK_PER_B);   // 32 * 16 = 512 blocks
    hinge_loss_kernel<<<grid, THREADS>>>(g_out, g_label, g_margin, result);
}

// round 2
// speedup vs baseline: 1.4183x; 1.4183x over previous
#include <cuda_runtime.h>
#include <cuda_bf16.h>

// Pairwise max-margin hinge loss, exploiting hinge(j,k)==hinge(k,j).
// loss = [ 2*sum_{strict-upper 32x32 tiles} + sum_{diag tiles (full)} ] / (N*2), over B batches.
//
// Inputs: out [N,B] f32, label [N,B] f32, margin [1] f32.  N=1024, B=32.

#define PN 1024
#define PB 32
#define TILE 32
#define NT (PN / TILE)                 // 32 tiles per dim
#define NTRI (NT * (NT + 1) / 2)       // 528 triangle tiles per batch
#define BLKS_PER_B 33                  // 528 / 33 = 16 tiles per block
#define THREADS 256                    // 8 warps -> 2 tiles per warp, exact
#define TILES_PER_BLOCK (NTRI / BLKS_PER_B)   // 16

// Transposed, interleaved scratch: g_T[b*PN + n] = (out, label)
__device__ float2 g_T[PB * PN];

__global__ __launch_bounds__(256)
void transpose_kernel(const float* __restrict__ g_out,
                      const float* __restrict__ g_label)
{
    int idx = blockIdx.x * blockDim.x + threadIdx.x;   // 0 .. PN*PB-1
    if (idx < PN * PB) {
        int n = idx >> 5;          // row in [N,B]
        int b = idx & 31;
        g_T[b * PN + n] = make_float2(g_out[idx], g_label[idx]);
    }
}

__device__ __forceinline__ int tri_offset(int r) {
    // number of tiles before row r in the (jt<=kt) triangle, NT=32
    return (r * (2 * NT + 1 - r)) >> 1;   // r*(65-r)/2
}

__global__ __launch_bounds__(THREADS)
void hinge_tri_kernel(const float* __restrict__ g_margin,
                      float* __restrict__ result)
{
    __shared__ float2 sm[PN];
    __shared__ float  warp_sums[THREADS / 32];

    const int batch  = blockIdx.x / BLKS_PER_B;
    const int bshare = blockIdx.x % BLKS_PER_B;
    const int t      = threadIdx.x;
    const int wid    = t >> 5;
    const int lane   = t & 31;

    // Stage this batch's 1024 (o,l) pairs: coalesced float4 loads, L2-hot.
    {
        const float4* src = (const float4*)(&g_T[batch * PN]);
        float4* dst = (float4*)sm;
        // 512 float4s, 256 threads -> 2 each
        dst[t]           = src[t];
        dst[t + THREADS] = src[t + THREADS];
    }
    __syncthreads();

    const float m = g_margin[0];

    float acc = 0.0f;

    // Each warp handles 2 consecutive triangle tiles.
    #pragma unroll
    for (int i = 0; i < TILES_PER_BLOCK / 8; i++) {   // 2 iterations
        int u = bshare * TILES_PER_BLOCK + wid * 2 + i;

        // decode u -> (jt, kt), jt <= kt
        float fr = (2.0f * NT + 1.0f
                    - sqrtf((2.0f * NT + 1.0f) * (2.0f * NT + 1.0f) - 8.0f * (float)u))
                   * 0.5f;
        int jt = (int)fr;
        while (tri_offset(jt + 1) <= u) jt++;
        while (tri_offset(jt) > u) jt--;
        int kt = jt + (u - tri_offset(jt));

        const float2 J = sm[jt * TILE + lane];
        const float oj = J.x;
        const float lj = J.y;
        const int kb = kt * TILE;

        float ts0 = 0.0f, ts1 = 0.0f;
        #pragma unroll
        for (int k = 0; k < TILE; k += 2) {
            float2 s0 = sm[kb + k];       // broadcast
            float2 s1 = sm[kb + k + 1];
            // m - (oj-ok)(lj-lk) == fma(ok-oj, lj-lk, m)
            float a0 = s0.x - oj, d0 = lj - s0.y;
            float a1 = s1.x - oj, d1 = lj - s1.y;
            ts0 += fmaxf(fmaf(a0, d0, m), 0.0f);
            ts1 += fmaxf(fmaf(a1, d1, m), 0.0f);
        }
        float ts = ts0 + ts1;
        float w = (jt == kt) ? 1.0f : 2.0f;
        acc = fmaf(w, ts, acc);
    }

    // Warp reduce
    #pragma unroll
    for (int off = 16; off > 0; off >>= 1)
        acc += __shfl_xor_sync(0xFFFFFFFFu, acc, off);

    if (lane == 0) warp_sums[wid] = acc;
    __syncthreads();

    if (wid == 0) {
        float s = (lane < THREADS / 32) ? warp_sums[lane] : 0.0f;
        #pragma unroll
        for (int off = 4; off > 0; off >>= 1)
            s += __shfl_xor_sync(0xFFFFFFFFu, s, off);
        if (lane == 0)
            atomicAdd(result, s * (1.0f / (PN * 2)));
    }
}

extern "C" void kernel_launch(void* const* d_in, const int* in_sizes, int n_in,
                              void* d_out, int out_size)
{
    const float* g_out    = (const float*)d_in[0];
    const float* g_label  = (const float*)d_in[1];
    const float* g_margin = (const float*)d_in[2];
    float*       result   = (float*)d_out;

    cudaMemsetAsync(result, 0, sizeof(float));

    transpose_kernel<<<(PN * PB + 255) / 256, 256>>>(g_out, g_label);

    dim3 grid(PB * BLKS_PER_B);   // 32 * 33 = 1056 blocks
    hinge_tri_kernel<<<grid, THREADS>>>(g_margin, result);
}

// round 3
// speedup vs baseline: 1.8063x; 1.2735x over previous
#include <cuda_runtime.h>
#include <cuda_bf16.h>

// Pairwise max-margin hinge loss, symmetry-halved, f32x2-packed inner loop.
// loss = [2*sum_{unordered off-diag 32x32 tiles} + sum_{diag tiles}] / (N*2), over B batches.
// Inputs: out [N,B] f32, label [N,B] f32, margin [1] f32.  N=1024, B=32.

#define PN 1024
#define PB 32
#define TILE 32
#define NT (PN / TILE)            // 32
#define NTRI 528                  // 480 (dt 1..15) + 16 (dt=16) + 32 (diag)
#define BLKS_PER_B 33
#define THREADS 128               // 4 warps; 4 tiles per warp; 16 tiles per block

// Transposed SoA scratch: g_on = -out, g_l = label, laid out [B][N].
__device__ float g_on[PB * PN];
__device__ float g_l [PB * PN];

__global__ __launch_bounds__(256)
void transpose_kernel(const float* __restrict__ g_out,
                      const float* __restrict__ g_label,
                      float* __restrict__ result)
{
    int idx = blockIdx.x * blockDim.x + threadIdx.x;   // 0 .. PN*PB-1
    if (idx < PN * PB) {
        int n = idx >> 5;
        int b = idx & 31;
        g_on[b * PN + n] = -g_out[idx];
        g_l [b * PN + n] =  g_label[idx];
    }
    if (idx == 0) *result = 0.0f;   // fold memset into this kernel
}

// Packed f32x2 add / fma (Blackwell). ptxas coalesces the pack/unpack movs
// into register pairing in the common case.
__device__ __forceinline__ float2 fadd2(float2 a, float2 b) {
    float2 d;
    asm("{.reg .b64 ra,rb,rd;\n\t"
        "mov.b64 ra,{%2,%3}; mov.b64 rb,{%4,%5};\n\t"
        "add.rn.f32x2 rd,ra,rb;\n\t"
        "mov.b64 {%0,%1},rd;}"
        : "=f"(d.x), "=f"(d.y)
        : "f"(a.x), "f"(a.y), "f"(b.x), "f"(b.y));
    return d;
}
__device__ __forceinline__ float2 ffma2(float2 a, float2 b, float2 c) {
    float2 d;
    asm("{.reg .b64 ra,rb,rc,rd;\n\t"
        "mov.b64 ra,{%2,%3}; mov.b64 rb,{%4,%5}; mov.b64 rc,{%6,%7};\n\t"
        "fma.rn.f32x2 rd,ra,rb,rc;\n\t"
        "mov.b64 {%0,%1},rd;}"
        : "=f"(d.x), "=f"(d.y)
        : "f"(a.x), "f"(a.y), "f"(b.x), "f"(b.y), "f"(c.x), "f"(c.y));
    return d;
}

__global__ __launch_bounds__(THREADS)
void hinge_tri_kernel(const float* __restrict__ g_margin,
                      float* __restrict__ result)
{
    __shared__ float s_on[PN];   // -o for this batch
    __shared__ float s_l [PN];   // +l for this batch
    __shared__ float warp_sums[THREADS / 32];

    const int batch  = blockIdx.x / BLKS_PER_B;
    const int bshare = blockIdx.x % BLKS_PER_B;     // 0..32, 16 tiles each
    const int t      = threadIdx.x;
    const int wid    = t >> 5;
    const int lane   = t & 31;

    // Stage: coalesced float4 loads (1024 floats per array, 128 threads -> 2 each).
    {
        const float4* so = (const float4*)(&g_on[batch * PN]);
        const float4* sl = (const float4*)(&g_l [batch * PN]);
        float4* don = (float4*)s_on;
        float4* dl  = (float4*)s_l;
        don[t]           = so[t];
        don[t + THREADS] = so[t + THREADS];
        dl [t]           = sl[t];
        dl [t + THREADS] = sl[t + THREADS];
    }
    __syncthreads();

    const float m = g_margin[0];
    const float2 mm = make_float2(m, m);

    float total = 0.0f;

    #pragma unroll
    for (int i = 0; i < 4; i++) {
        const int u = bshare * 16 + wid * 4 + i;      // 0..527

        // Decode: circular-distance tiling of the unordered tile pairs.
        int jt, kt;
        float w;
        if (u < 480)      { int dt = (u >> 5) + 1; jt = u & 31; kt = (jt + dt) & 31; w = 2.0f; }
        else if (u < 496) { jt = u - 480; kt = jt + 16; w = 2.0f; }
        else              { jt = u - 496; kt = jt;      w = 1.0f; }

        const float oj  = -s_on[jt * TILE + lane];    // +o_j
        const float ljn = -s_l [jt * TILE + lane];    // -l_j
        const float2 ojp  = make_float2(oj, oj);
        const float2 ljnp = make_float2(ljn, ljn);
        const int kb = kt * TILE;

        float2 accA = make_float2(0.0f, 0.0f);
        float2 accB = make_float2(0.0f, 0.0f);

        #pragma unroll
        for (int k = 0; k < TILE; k += 4) {
            // Broadcast LDS.128: 4 consecutive k values per array.
            float4 o4 = *(const float4*)(&s_on[kb + k]);   // -o_k
            float4 l4 = *(const float4*)(&s_l [kb + k]);   // +l_k

            // a = oj - ok ; d' = lk - lj ; v = m + a*d' = m - (oj-ok)(lj-lk)
            float2 a01 = fadd2(ojp,  make_float2(o4.x, o4.y));
            float2 a23 = fadd2(ojp,  make_float2(o4.z, o4.w));
            float2 d01 = fadd2(ljnp, make_float2(l4.x, l4.y));
            float2 d23 = fadd2(ljnp, make_float2(l4.z, l4.w));
            float2 v01 = ffma2(a01, d01, mm);
            float2 v23 = ffma2(a23, d23, mm);

            accA = fadd2(accA, make_float2(fmaxf(v01.x, 0.0f), fmaxf(v01.y, 0.0f)));
            accB = fadd2(accB, make_float2(fmaxf(v23.x, 0.0f), fmaxf(v23.y, 0.0f)));
        }

        float ts = (accA.x + accA.y) + (accB.x + accB.y);
        total = fmaf(w, ts, total);
    }

    // Warp reduce
    #pragma unroll
    for (int off = 16; off > 0; off >>= 1)
        total += __shfl_xor_sync(0xFFFFFFFFu, total, off);

    if (lane == 0) warp_sums[wid] = total;
    __syncthreads();

    if (t == 0) {
        float s = warp_sums[0] + warp_sums[1] + warp_sums[2] + warp_sums[3];
        atomicAdd(result, s * (1.0f / (PN * 2)));
    }
}

extern "C" void kernel_launch(void* const* d_in, const int* in_sizes, int n_in,
                              void* d_out, int out_size)
{
    const float* g_out    = (const float*)d_in[0];
    const float* g_label  = (const float*)d_in[1];
    const float* g_margin = (const float*)d_in[2];
    float*       result   = (float*)d_out;

    transpose_kernel<<<(PN * PB + 255) / 256, 256>>>(g_out, g_label, result);

    dim3 grid(PB * BLKS_PER_B);   // 1056 blocks
    hinge_tri_kernel<<<grid, THREADS>>>(g_margin, result);
}